// round 15
// baseline (speedup 1.0000x reference)
#include <cuda_runtime.h>
#include <math.h>

// SpectralAngleLoss R15: persistent-CTA version of the proven R10 body.
// 1184 CTAs (148 SMs x 8), each loops over ~7 rows; per-row body identical to
// R10 (smem-atomic scatter at the ATOMS ceiling, gather-form norms, fire-and-
// forget float RED accumulate). Separate 1-warp finalize (R10-proven tail).

#define N_PEAKS   256
#define NUM_BINS  2000
#define NB_PAD    2048
#define MAX_ROWS  8192
#define THREADS   256
#define GRID_CTAS 1184            // 148 x 8: one wave, no CTA churn

__device__ float g_accum = 0.0f;  // reset by finalize each replay

__device__ __forceinline__ int mz_bin(float mz) {
    int b = (int)(mz * 2000.0f);           // trunc toward zero == astype(int32)
    return min(max(b, 0), NUM_BINS - 1);
}

__global__ __launch_bounds__(THREADS, 8)
void sal_body(const float* __restrict__ pred_mz,
              const float* __restrict__ pred_int,
              const float* __restrict__ targ_mz,
              const float* __restrict__ targ_int,
              const float* __restrict__ targ_mask,
              int rows)
{
    __shared__ __align__(16) float ph[NB_PAD];
    __shared__ __align__(16) float th[NB_PAD];
    __shared__ float red[3][THREADS / 32];

    const int tid = threadIdx.x;

    for (int row = blockIdx.x; row < rows; row += GRID_CTAS) {
        // ---- issue global loads FIRST (bury 577-cyc DRAM latency under zero)
        const int idx = row * N_PEAKS + tid;
        const float mzp = pred_mz[idx];
        const float ip  = pred_int[idx];
        const float mzt = targ_mz[idx];
        const float it  = targ_int[idx];
        const float ms  = targ_mask[idx];

        // ---- zero both histograms (safe: previous row's gather completed at
        //      the barrier after red[] write below)
        {
            float4 z = make_float4(0.f, 0.f, 0.f, 0.f);
            float4* p4 = (float4*)ph;
            float4* t4 = (float4*)th;
            #pragma unroll
            for (int i = 0; i < NB_PAD / 4 / THREADS; i++) {   // 2 iters
                p4[tid + i * THREADS] = z;
                t4[tid + i * THREADS] = z;
            }
        }

        const int   bp  = mz_bin(mzp);
        const int   bt  = mz_bin(mzt);
        const float itm = it * ms;
        __syncthreads();                               // zero done

        // ---- scatter: 2 spread smem atomics per thread (the hardware floor)
        atomicAdd(&ph[bp], ip);
        atomicAdd(&th[bt], itm);
        __syncthreads();                               // scatter done

        // ---- gather-form reductions: 3 LDS per thread, no bin scan
        float dot = ip  * th[bp];
        float pn  = ip  * ph[bp];
        float tn  = itm * th[bt];

        #pragma unroll
        for (int o = 16; o > 0; o >>= 1) {
            dot += __shfl_xor_sync(0xFFFFFFFFu, dot, o);
            pn  += __shfl_xor_sync(0xFFFFFFFFu, pn,  o);
            tn  += __shfl_xor_sync(0xFFFFFFFFu, tn,  o);
        }
        if ((tid & 31) == 0) {
            int w = tid >> 5;
            red[0][w] = dot; red[1][w] = pn; red[2][w] = tn;
        }
        __syncthreads();                 // red ready; gathers done -> next zero ok

        if (tid == 0) {
            float d = 0.f, a = 0.f, b = 0.f;
            #pragma unroll
            for (int w = 0; w < THREADS / 32; w++) {
                d += red[0][w]; a += red[1][w]; b += red[2][w];
            }
            const float eps = 1e-8f;
            float c = d / (fmaxf(sqrtf(a), eps) * fmaxf(sqrtf(b), eps));
            c = fminf(fmaxf(c, -1.0f), 1.0f);
            atomicAdd(&g_accum, acosf(c));   // fire-and-forget RED.ADD.F32
        }
    }
}

__global__ void sal_finalize(float* __restrict__ out, int rows)
{
    if (threadIdx.x == 0) {
        out[0] = g_accum / ((float)rows * 3.14159265358979323846f);
        g_accum = 0.0f;                      // reset for the next graph replay
    }
}

extern "C" void kernel_launch(void* const* d_in, const int* in_sizes, int n_in,
                              void* d_out, int out_size)
{
    const float* pred_mz   = (const float*)d_in[0];
    const float* pred_int  = (const float*)d_in[1];
    const float* targ_mz   = (const float*)d_in[2];
    const float* targ_int  = (const float*)d_in[3];
    const float* targ_mask = (const float*)d_in[4];
    float* out = (float*)d_out;

    int rows = in_sizes[0] / N_PEAKS;
    if (rows > MAX_ROWS) rows = MAX_ROWS;

    sal_body<<<GRID_CTAS, THREADS>>>(pred_mz, pred_int, targ_mz, targ_int,
                                     targ_mask, rows);
    sal_finalize<<<1, 32>>>(out, rows);
}

// round 16
// speedup vs baseline: 1.0286x; 1.0286x over previous
#include <cuda_runtime.h>
#include <math.h>

// SpectralAngleLoss R16: proven R10 body (block-per-row smem-atomic scatter at
// the ATOMS throughput ceiling, gather-form norms). Tail: each CTA RED.ADDs its
// pre-scaled angle directly into d_out[0]; a cudaMemsetAsync node zeroes
// d_out at the start of every graph replay. No finalize kernel, no device
// globals, no fences, no return-value atomics.

#define N_PEAKS   256
#define NUM_BINS  2000
#define NB_PAD    2048
#define MAX_ROWS  8192
#define THREADS   256

__device__ __forceinline__ int mz_bin(float mz) {
    int b = (int)(mz * 2000.0f);           // trunc toward zero == astype(int32)
    return min(max(b, 0), NUM_BINS - 1);
}

__global__ __launch_bounds__(THREADS)
void sal_row(const float* __restrict__ pred_mz,
             const float* __restrict__ pred_int,
             const float* __restrict__ targ_mz,
             const float* __restrict__ targ_int,
             const float* __restrict__ targ_mask,
             float* __restrict__ out, float inv_rows_pi)
{
    __shared__ __align__(16) float ph[NB_PAD];
    __shared__ __align__(16) float th[NB_PAD];
    __shared__ float red[3][THREADS / 32];

    const int row = blockIdx.x;
    const int tid = threadIdx.x;

    // ---- zero both histograms (2 STS.128 per thread per array, exact)
    {
        float4 z = make_float4(0.f, 0.f, 0.f, 0.f);
        float4* p4 = (float4*)ph;
        float4* t4 = (float4*)th;
        #pragma unroll
        for (int i = 0; i < NB_PAD / 4 / THREADS; i++) {   // 2 iters
            p4[tid + i * THREADS] = z;
            t4[tid + i * THREADS] = z;
        }
    }

    // ---- coalesced loads, one element per thread
    const int idx = row * N_PEAKS + tid;
    const float ip  = pred_int[idx];
    const float itm = targ_int[idx] * targ_mask[idx];
    const int   bp  = mz_bin(pred_mz[idx]);
    const int   bt  = mz_bin(targ_mz[idx]);
    __syncthreads();

    // ---- scatter: 2 spread smem atomics per thread (the hardware floor)
    atomicAdd(&ph[bp], ip);
    atomicAdd(&th[bt], itm);
    __syncthreads();

    // ---- gather-form reductions: 3 LDS per thread, no bin scan
    float dot = ip  * th[bp];
    float pn  = ip  * ph[bp];
    float tn  = itm * th[bt];

    #pragma unroll
    for (int o = 16; o > 0; o >>= 1) {
        dot += __shfl_xor_sync(0xFFFFFFFFu, dot, o);
        pn  += __shfl_xor_sync(0xFFFFFFFFu, pn,  o);
        tn  += __shfl_xor_sync(0xFFFFFFFFu, tn,  o);
    }
    if ((tid & 31) == 0) {
        int w = tid >> 5;
        red[0][w] = dot; red[1][w] = pn; red[2][w] = tn;
    }
    __syncthreads();

    if (tid == 0) {
        float d = 0.f, a = 0.f, b = 0.f;
        #pragma unroll
        for (int w = 0; w < THREADS / 32; w++) {
            d += red[0][w]; a += red[1][w]; b += red[2][w];
        }
        const float eps = 1e-8f;
        float c = d / (fmaxf(sqrtf(a), eps) * fmaxf(sqrtf(b), eps));
        c = fminf(fmaxf(c, -1.0f), 1.0f);
        // fire-and-forget pre-scaled contribution straight into the output;
        // d_out[0] is zeroed by the memset node at the start of each replay.
        atomicAdd(out, acosf(c) * inv_rows_pi);
    }
}

extern "C" void kernel_launch(void* const* d_in, const int* in_sizes, int n_in,
                              void* d_out, int out_size)
{
    const float* pred_mz   = (const float*)d_in[0];
    const float* pred_int  = (const float*)d_in[1];
    const float* targ_mz   = (const float*)d_in[2];
    const float* targ_int  = (const float*)d_in[3];
    const float* targ_mask = (const float*)d_in[4];
    float* out = (float*)d_out;

    int rows = in_sizes[0] / N_PEAKS;
    if (rows > MAX_ROWS) rows = MAX_ROWS;
    float inv_rows_pi = 1.0f / ((float)rows * 3.14159265358979323846f);

    // Zero the output accumulator (graph-capturable memset node; runs at the
    // start of every replay, clearing the harness's 0xAA poison too).
    cudaMemsetAsync(d_out, 0, sizeof(float));

    sal_row<<<rows, THREADS>>>(pred_mz, pred_int, targ_mz, targ_int,
                               targ_mask, out, inv_rows_pi);
}

// round 17
// speedup vs baseline: 1.0986x; 1.0681x over previous
#include <cuda_runtime.h>
#include <math.h>

// SpectralAngleLoss R17: single-kernel, single-graph-node version.
// Body identical to the measured 22.6us R16 body (block-per-row smem-atomic
// scatter at the ATOMS ceiling, gather-form norms). Tail: fire-and-forget
// pre-scaled RED.ADD.F32 into d_out[0]. Reset: CTA 0 tid 0 atomicExch(out,0)
// as its FIRST instruction — lands at L2 >=700 cycles before the earliest
// possible contribution (every CTA needs ~800 cycles of body work first).

#define N_PEAKS   256
#define NUM_BINS  2000
#define NB_PAD    2048
#define MAX_ROWS  8192
#define THREADS   256

__device__ __forceinline__ int mz_bin(float mz) {
    int b = (int)(mz * 2000.0f);           // trunc toward zero == astype(int32)
    return min(max(b, 0), NUM_BINS - 1);
}

__global__ __launch_bounds__(THREADS)
void sal_row(const float* __restrict__ pred_mz,
             const float* __restrict__ pred_int,
             const float* __restrict__ targ_mz,
             const float* __restrict__ targ_int,
             const float* __restrict__ targ_mask,
             float* __restrict__ out, float inv_rows_pi)
{
    // ---- FIRST instruction of bid 0: zero the output accumulator.
    // bid 0 is dispatched first; its exch reaches out's L2 slice long before
    // any CTA's tail RED (each CTA has >=800 cycles of work before its add).
    if (blockIdx.x == 0 && threadIdx.x == 0) {
        atomicExch(out, 0.0f);
    }

    __shared__ __align__(16) float ph[NB_PAD];
    __shared__ __align__(16) float th[NB_PAD];
    __shared__ float red[3][THREADS / 32];

    const int row = blockIdx.x;
    const int tid = threadIdx.x;

    // ---- zero both histograms (2 STS.128 per thread per array, exact)
    {
        float4 z = make_float4(0.f, 0.f, 0.f, 0.f);
        float4* p4 = (float4*)ph;
        float4* t4 = (float4*)th;
        #pragma unroll
        for (int i = 0; i < NB_PAD / 4 / THREADS; i++) {   // 2 iters
            p4[tid + i * THREADS] = z;
            t4[tid + i * THREADS] = z;
        }
    }

    // ---- coalesced loads, one element per thread
    const int idx = row * N_PEAKS + tid;
    const float ip  = pred_int[idx];
    const float itm = targ_int[idx] * targ_mask[idx];
    const int   bp  = mz_bin(pred_mz[idx]);
    const int   bt  = mz_bin(targ_mz[idx]);
    __syncthreads();

    // ---- scatter: 2 spread smem atomics per thread (the hardware floor)
    atomicAdd(&ph[bp], ip);
    atomicAdd(&th[bt], itm);
    __syncthreads();

    // ---- gather-form reductions: 3 LDS per thread, no bin scan
    float dot = ip  * th[bp];
    float pn  = ip  * ph[bp];
    float tn  = itm * th[bt];

    #pragma unroll
    for (int o = 16; o > 0; o >>= 1) {
        dot += __shfl_xor_sync(0xFFFFFFFFu, dot, o);
        pn  += __shfl_xor_sync(0xFFFFFFFFu, pn,  o);
        tn  += __shfl_xor_sync(0xFFFFFFFFu, tn,  o);
    }
    if ((tid & 31) == 0) {
        int w = tid >> 5;
        red[0][w] = dot; red[1][w] = pn; red[2][w] = tn;
    }
    __syncthreads();

    if (tid == 0) {
        float d = 0.f, a = 0.f, b = 0.f;
        #pragma unroll
        for (int w = 0; w < THREADS / 32; w++) {
            d += red[0][w]; a += red[1][w]; b += red[2][w];
        }
        const float eps = 1e-8f;
        float c = d / (fmaxf(sqrtf(a), eps) * fmaxf(sqrtf(b), eps));
        c = fminf(fmaxf(c, -1.0f), 1.0f);
        // fire-and-forget pre-scaled contribution straight into the output
        atomicAdd(out, acosf(c) * inv_rows_pi);
    }
}

extern "C" void kernel_launch(void* const* d_in, const int* in_sizes, int n_in,
                              void* d_out, int out_size)
{
    const float* pred_mz   = (const float*)d_in[0];
    const float* pred_int  = (const float*)d_in[1];
    const float* targ_mz   = (const float*)d_in[2];
    const float* targ_int  = (const float*)d_in[3];
    const float* targ_mask = (const float*)d_in[4];
    float* out = (float*)d_out;

    int rows = in_sizes[0] / N_PEAKS;
    if (rows > MAX_ROWS) rows = MAX_ROWS;
    float inv_rows_pi = 1.0f / ((float)rows * 3.14159265358979323846f);

    sal_row<<<rows, THREADS>>>(pred_mz, pred_int, targ_mz, targ_int,
                               targ_mask, out, inv_rows_pi);
}